// round 1
// baseline (speedup 1.0000x reference)
#include <cuda_runtime.h>

#define DIM   192
#define TDIM  576          // 3*DIM
#define HEADS 6
#define WSZ   8
#define PIX   64           // WSZ*WSZ
#define IMG   256
#define SHIFTV 4

// smem layout (floats)
#define XS_OFF 0
#define RS_OFF 12288
#define QS_OFF 24576
#define KS_OFF 36864
#define AS_OFF 49152
#define SMEM_FLOATS (49152 + 6144)   // 55296 floats = 221184 bytes

// Pre-transposed weights: [c][o] layouts for coalesced per-k row loads.
__device__ float g_qkvT[DIM * TDIM];   // [c][o], stride TDIM
__device__ float g_projT[DIM * DIM];   // [c][o], stride DIM

__global__ void wtrans_kernel(const float* __restrict__ qkv_w,
                              const float* __restrict__ proj_w) {
    int i = blockIdx.x * 256 + threadIdx.x;
    if (i < TDIM * DIM) {
        int o = i / DIM, c = i % DIM;
        g_qkvT[c * TDIM + o] = qkv_w[i];
    }
    if (i < DIM * DIM) {
        int o = i / DIM, c = i % DIM;
        g_projT[c * DIM + o] = proj_w[i];
    }
}

// D[192x64] = W[192x192-slice] @ src[192x64], weights from gmem (transposed),
// src/dst in smem. Thread tile: 12 rows x 4 cols (float4).
__device__ __forceinline__ void gemm192_smem(const float* __restrict__ wT, int wstride,
                                             int ooff, const float* src, float* dst,
                                             int rg, int cg) {
    float4 acc[12];
#pragma unroll
    for (int r = 0; r < 12; r++) acc[r] = make_float4(0.f, 0.f, 0.f, 0.f);
    const float4* s4 = (const float4*)src;
#pragma unroll 4
    for (int c = 0; c < DIM; c++) {
        float4 xv = s4[c * 16 + cg];
        const float4* wrow = (const float4*)(wT + (size_t)c * wstride + ooff + rg * 12);
        float4 w0 = __ldg(wrow), w1 = __ldg(wrow + 1), w2 = __ldg(wrow + 2);
        float wv[12];
        wv[0] = w0.x; wv[1] = w0.y; wv[2]  = w0.z; wv[3]  = w0.w;
        wv[4] = w1.x; wv[5] = w1.y; wv[6]  = w1.z; wv[7]  = w1.w;
        wv[8] = w2.x; wv[9] = w2.y; wv[10] = w2.z; wv[11] = w2.w;
#pragma unroll
        for (int r = 0; r < 12; r++) {
            acc[r].x += wv[r] * xv.x;
            acc[r].y += wv[r] * xv.y;
            acc[r].z += wv[r] * xv.z;
            acc[r].w += wv[r] * xv.w;
        }
    }
    float4* d4 = (float4*)dst;
#pragma unroll
    for (int r = 0; r < 12; r++) d4[(rg * 12 + r) * 16 + cg] = acc[r];
}

// Depthwise 3x3, zero-padded within the 8x8 window.
__device__ __forceinline__ void dwconv(const float* Rsrc, float* dst,
                                       const float* __restrict__ dww, int tofs, int tid) {
    for (int e = tid; e < DIM * PIX; e += 256) {
        int o = e >> 6, p = e & 63, i = p >> 3, j = p & 7;
        const float* wd = dww + (size_t)(tofs + o) * 9;
        const float* rr = Rsrc + o * 64;
        float s = 0.f;
#pragma unroll
        for (int di = 0; di < 3; di++) {
            int ii = i + di - 1;
            if ((unsigned)ii < 8u) {
#pragma unroll
                for (int dj = 0; dj < 3; dj++) {
                    int jj = j + dj - 1;
                    if ((unsigned)jj < 8u)
                        s += rr[ii * 8 + jj] * __ldg(wd + di * 3 + dj);
                }
            }
        }
        dst[e] = s;
    }
}

__global__ void __launch_bounds__(256, 1)
attn_kernel(const float* __restrict__ x, const float* __restrict__ dw_w,
            const float* __restrict__ temperature, float* __restrict__ out) {
    extern __shared__ float sm[];
    float* Xs = sm + XS_OFF;   // window input [192][64]
    float* Rs = sm + RS_OFF;   // raw conv input [192][64]
    float* Qs = sm + QS_OFF;   // q, later attention output [192][64]
    float* Ks = sm + KS_OFF;   // k, later v [192][64]
    float* As = sm + AS_OFF;   // rsum(384) then attn [192][32]

    const int tid = threadIdx.x;
    const int win = blockIdx.x;
    const int bi = win >> 10;
    const int wh = (win >> 5) & 31;
    const int ww = win & 31;
    const int rg = tid >> 4;   // 16 groups of 12 rows
    const int cg = tid & 15;   // 16 float4 columns
    const int lane = tid & 31;

    // ---- load window with roll(-4, -4) ----
    {
        const float* xb = x + (size_t)bi * DIM * IMG * IMG;
        for (int e = tid; e < DIM * PIX; e += 256) {
            int c = e >> 6, p = e & 63;
            int i = p >> 3, j = p & 7;
            int gh = (wh * WSZ + i + SHIFTV) & 255;
            int gw = (ww * WSZ + j + SHIFTV) & 255;
            Xs[e] = xb[(c * IMG + gh) * IMG + gw];
        }
    }
    __syncthreads();

    // ---- q ----
    gemm192_smem(g_qkvT, TDIM, 0, Xs, Rs, rg, cg);
    __syncthreads();
    dwconv(Rs, Qs, dw_w, 0, tid);
    __syncthreads();
    // ---- k ----
    gemm192_smem(g_qkvT, TDIM, DIM, Xs, Rs, rg, cg);
    __syncthreads();
    dwconv(Rs, Ks, dw_w, DIM, tid);
    __syncthreads();

    // ---- l2 normalize q, k over the 64 pixels (rsum lives in As[0..384)) ----
    for (int r = tid; r < 2 * DIM; r += 256) As[r] = 0.f;
    __syncthreads();
    for (int v = tid; v < 2 * 3072; v += 256) {
        int which = v >= 3072;
        int f = v - which * 3072;
        const float4* t4 = (const float4*)(which ? Ks : Qs);
        float4 q = t4[f];
        float ss = q.x * q.x + q.y * q.y + q.z * q.z + q.w * q.w;
        ss += __shfl_xor_sync(0xffffffffu, ss, 8);
        ss += __shfl_xor_sync(0xffffffffu, ss, 4);
        ss += __shfl_xor_sync(0xffffffffu, ss, 2);
        ss += __shfl_xor_sync(0xffffffffu, ss, 1);
        if ((lane & 15) == 0) atomicAdd(&As[which * DIM + (f >> 4)], ss);
    }
    __syncthreads();
    for (int r = tid; r < 2 * DIM; r += 256)
        As[r] = 1.f / fmaxf(sqrtf(As[r]), 1e-12f);
    __syncthreads();
    for (int v = tid; v < 2 * 3072; v += 256) {
        int which = v >= 3072;
        int f = v - which * 3072;
        float4* t4 = (float4*)(which ? Ks : Qs);
        float sc = As[which * DIM + (f >> 4)];
        float4 q = t4[f];
        q.x *= sc; q.y *= sc; q.z *= sc; q.w *= sc;
        t4[f] = q;
    }
    __syncthreads();

    // ---- attn scores: As[row][d] = (q_row . k_{head,d}) * temp[head] ----
    {
        float aacc[12][2];
#pragma unroll
        for (int r = 0; r < 12; r++) { aacc[r][0] = 0.f; aacc[r][1] = 0.f; }
        const float4* q4 = (const float4*)Qs;
        const float4* k4 = (const float4*)Ks;
#pragma unroll 2
        for (int p4 = 0; p4 < 16; p4++) {
#pragma unroll
            for (int r = 0; r < 12; r++) {
                int row = rg * 12 + r;
                int base = row & ~31;
                float4 qv = q4[row * 16 + p4];
#pragma unroll
                for (int cI = 0; cI < 2; cI++) {
                    float4 kv = k4[(base + cg * 2 + cI) * 16 + p4];
                    aacc[r][cI] += qv.x * kv.x + qv.y * kv.y + qv.z * kv.z + qv.w * kv.w;
                }
            }
        }
        __syncthreads();   // rsum region about to be overwritten by scores
#pragma unroll
        for (int r = 0; r < 12; r++) {
            int row = rg * 12 + r;
            float tmp = __ldg(temperature + (row >> 5));
            As[row * 32 + cg * 2]     = aacc[r][0] * tmp;
            As[row * 32 + cg * 2 + 1] = aacc[r][1] * tmp;
        }
    }
    __syncthreads();

    // ---- softmax over d (32), one row per thread ----
    if (tid < DIM) {
        float* arow = As + tid * 32;
        float m = arow[0];
#pragma unroll
        for (int d = 1; d < 32; d++) m = fmaxf(m, arow[d]);
        float s = 0.f;
#pragma unroll
        for (int d = 0; d < 32; d++) { float e = expf(arow[d] - m); arow[d] = e; s += e; }
        float inv = 1.f / s;
#pragma unroll
        for (int d = 0; d < 32; d++) arow[d] *= inv;
    }
    __syncthreads();

    // ---- v ----
    gemm192_smem(g_qkvT, TDIM, 2 * DIM, Xs, Rs, rg, cg);
    __syncthreads();
    dwconv(Rs, Ks, dw_w, 2 * DIM, tid);   // V into Ks
    __syncthreads();

    // ---- out = attn @ v  -> Qs ----
    {
        float4 acc[12];
#pragma unroll
        for (int r = 0; r < 12; r++) acc[r] = make_float4(0.f, 0.f, 0.f, 0.f);
        const float4* v4 = (const float4*)Ks;
        for (int d = 0; d < 32; d++) {
#pragma unroll
            for (int r = 0; r < 12; r++) {
                int row = rg * 12 + r;
                float a = As[row * 32 + d];
                float4 vv = v4[((row & ~31) + d) * 16 + cg];
                acc[r].x += a * vv.x;
                acc[r].y += a * vv.y;
                acc[r].z += a * vv.z;
                acc[r].w += a * vv.w;
            }
        }
        float4* o4 = (float4*)Qs;
#pragma unroll
        for (int r = 0; r < 12; r++) o4[(rg * 12 + r) * 16 + cg] = acc[r];
    }
    __syncthreads();

    // ---- proj GEMM, store to gmem with roll(+4, +4) ----
    {
        float4 acc[12];
#pragma unroll
        for (int r = 0; r < 12; r++) acc[r] = make_float4(0.f, 0.f, 0.f, 0.f);
        const float4* s4 = (const float4*)Qs;
#pragma unroll 4
        for (int c = 0; c < DIM; c++) {
            float4 xv = s4[c * 16 + cg];
            const float4* wrow = (const float4*)(g_projT + (size_t)c * DIM + rg * 12);
            float4 w0 = __ldg(wrow), w1 = __ldg(wrow + 1), w2 = __ldg(wrow + 2);
            float wv[12];
            wv[0] = w0.x; wv[1] = w0.y; wv[2]  = w0.z; wv[3]  = w0.w;
            wv[4] = w1.x; wv[5] = w1.y; wv[6]  = w1.z; wv[7]  = w1.w;
            wv[8] = w2.x; wv[9] = w2.y; wv[10] = w2.z; wv[11] = w2.w;
#pragma unroll
            for (int r = 0; r < 12; r++) {
                acc[r].x += wv[r] * xv.x;
                acc[r].y += wv[r] * xv.y;
                acc[r].z += wv[r] * xv.z;
                acc[r].w += wv[r] * xv.w;
            }
        }
        int i = (cg * 4) >> 3;                 // same row-within-window for all 4 cols
        int gh = (wh * WSZ + i + SHIFTV) & 255;
#pragma unroll
        for (int r = 0; r < 12; r++) {
            int o = rg * 12 + r;
            float* orow = out + ((size_t)(bi * DIM + o) * IMG + gh) * IMG;
            float vals[4] = {acc[r].x, acc[r].y, acc[r].z, acc[r].w};
#pragma unroll
            for (int u = 0; u < 4; u++) {
                int j = (cg * 4 + u) & 7;
                int gw = (ww * WSZ + j + SHIFTV) & 255;
                orow[gw] = vals[u];
            }
        }
    }
}

extern "C" void kernel_launch(void* const* d_in, const int* in_sizes, int n_in,
                              void* d_out, int out_size) {
    const float* x           = (const float*)d_in[0];
    const float* qkv_w       = (const float*)d_in[1];
    const float* dw_w        = (const float*)d_in[2];
    const float* proj_w      = (const float*)d_in[3];
    const float* temperature = (const float*)d_in[4];
    float* out = (float*)d_out;

    cudaFuncSetAttribute(attn_kernel, cudaFuncAttributeMaxDynamicSharedMemorySize,
                         SMEM_FLOATS * 4);
    wtrans_kernel<<<(TDIM * DIM + 255) / 256, 256>>>(qkv_w, proj_w);
    attn_kernel<<<4096, 256, SMEM_FLOATS * 4>>>(x, dw_w, temperature, out);
}

// round 2
// speedup vs baseline: 1.1871x; 1.1871x over previous
#include <cuda_runtime.h>

#define DIM   192
#define TDIM  576          // 3*DIM
#define WSZ   8
#define PIX   64
#define IMG   256
#define SHIFTV 4
#define NTHR  512

// smem layout (floats)
#define XS_OFF 0
#define RS_OFF 12288
#define QS_OFF 24576
#define KS_OFF 36864
#define AS_OFF 49152
#define SMEM_FLOATS (49152 + 6144)   // 221184 bytes

typedef unsigned long long ull;

// Pre-transposed weights: [c][o] layout for contiguous per-k row-pair loads.
__device__ float g_qkvT[DIM * TDIM];
__device__ float g_projT[DIM * DIM];

__global__ void wtrans_kernel(const float* __restrict__ qkv_w,
                              const float* __restrict__ proj_w) {
    int i = blockIdx.x * 256 + threadIdx.x;
    if (i < TDIM * DIM) {
        int o = i / DIM, c = i % DIM;
        g_qkvT[c * TDIM + o] = qkv_w[i];
    }
    if (i < DIM * DIM) {
        int o = i / DIM, c = i % DIM;
        g_projT[c * DIM + o] = proj_w[i];
    }
}

__device__ __forceinline__ ull dup2(float v) {
    ull r;
    asm("mov.b64 %0, {%1, %1};" : "=l"(r) : "f"(v));
    return r;
}
__device__ __forceinline__ void ffma2(ull& d, ull a, ull b) {
    asm("fma.rn.f32x2 %0, %1, %2, %0;" : "+l"(d) : "l"(a), "l"(b));
}
__device__ __forceinline__ float2 ull2f2(ull v) {
    float2 r;
    asm("mov.b64 {%0, %1}, %2;" : "=f"(r.x), "=f"(r.y) : "l"(v));
    return r;
}

// D[192x64] = W_slice[192x192]^T-applied @ src[192x64].
// 512 threads: rg=tid>>4 (32 groups x 6 rows), cg=tid&15 (float4 col).
// Accumulators are row-pairs packed in f32x2.
__device__ __forceinline__ void gemm192v2(const float* __restrict__ wT, int wstride,
                                          int ooff, const float* src, float* dst,
                                          int rg, int cg) {
    ull acc[3][4];
#pragma unroll
    for (int p = 0; p < 3; p++)
#pragma unroll
        for (int j = 0; j < 4; j++) acc[p][j] = 0ull;
    const float4* s4 = (const float4*)src;
#pragma unroll 4
    for (int c = 0; c < DIM; c++) {
        float4 xv = s4[c * 16 + cg];
        const ull* wrow = (const ull*)(wT + (size_t)c * wstride + ooff + rg * 6);
        ull w0 = __ldg(wrow), w1 = __ldg(wrow + 1), w2 = __ldg(wrow + 2);
        ull xd0 = dup2(xv.x), xd1 = dup2(xv.y), xd2 = dup2(xv.z), xd3 = dup2(xv.w);
        ffma2(acc[0][0], w0, xd0); ffma2(acc[1][0], w1, xd0); ffma2(acc[2][0], w2, xd0);
        ffma2(acc[0][1], w0, xd1); ffma2(acc[1][1], w1, xd1); ffma2(acc[2][1], w2, xd1);
        ffma2(acc[0][2], w0, xd2); ffma2(acc[1][2], w1, xd2); ffma2(acc[2][2], w2, xd2);
        ffma2(acc[0][3], w0, xd3); ffma2(acc[1][3], w1, xd3); ffma2(acc[2][3], w2, xd3);
    }
    float4* d4 = (float4*)dst;
#pragma unroll
    for (int p = 0; p < 3; p++) {
        float2 f0 = ull2f2(acc[p][0]), f1 = ull2f2(acc[p][1]);
        float2 f2 = ull2f2(acc[p][2]), f3 = ull2f2(acc[p][3]);
        d4[(rg * 6 + 2 * p) * 16 + cg]     = make_float4(f0.x, f1.x, f2.x, f3.x);
        d4[(rg * 6 + 2 * p + 1) * 16 + cg] = make_float4(f0.y, f1.y, f2.y, f3.y);
    }
}

// Depthwise 3x3, zero-padded within the 8x8 window.
__device__ __forceinline__ void dwconv(const float* Rsrc, float* dst,
                                       const float* __restrict__ dww, int tofs, int tid) {
    for (int e = tid; e < DIM * PIX; e += NTHR) {
        int o = e >> 6, p = e & 63, i = p >> 3, j = p & 7;
        const float* wd = dww + (size_t)(tofs + o) * 9;
        const float* rr = Rsrc + o * 64;
        float s = 0.f;
#pragma unroll
        for (int di = 0; di < 3; di++) {
            int ii = i + di - 1;
            if ((unsigned)ii < 8u) {
#pragma unroll
                for (int dj = 0; dj < 3; dj++) {
                    int jj = j + dj - 1;
                    if ((unsigned)jj < 8u)
                        s += rr[ii * 8 + jj] * __ldg(wd + di * 3 + dj);
                }
            }
        }
        dst[e] = s;
    }
}

__global__ void __launch_bounds__(NTHR, 1)
attn_kernel(const float* __restrict__ x, const float* __restrict__ dw_w,
            const float* __restrict__ temperature, float* __restrict__ out) {
    extern __shared__ float sm[];
    float* Xs = sm + XS_OFF;   // window input [192][64]
    float* Rs = sm + RS_OFF;   // raw conv output [192][64]
    float* Qs = sm + QS_OFF;   // q, later attention output [192][64]
    float* Ks = sm + KS_OFF;   // k, later v [192][64]
    float* As = sm + AS_OFF;   // rsum(384) then attn [192][32]

    const int tid = threadIdx.x;
    const int win = blockIdx.x;
    const int bi = win >> 10;
    const int wh = (win >> 5) & 31;
    const int ww = win & 31;
    const int rg = tid >> 4;   // 32 groups of 6 rows
    const int cg = tid & 15;   // 16 float4 columns
    const int lane = tid & 31;

    // ---- load window with roll(-4, -4) ----
    {
        const float* xb = x + (size_t)bi * DIM * IMG * IMG;
        for (int e = tid; e < DIM * PIX; e += NTHR) {
            int c = e >> 6, p = e & 63;
            int i = p >> 3, j = p & 7;
            int gh = (wh * WSZ + i + SHIFTV) & 255;
            int gw = (ww * WSZ + j + SHIFTV) & 255;
            Xs[e] = xb[(c * IMG + gh) * IMG + gw];
        }
    }
    __syncthreads();

    // ---- q ----
    gemm192v2(g_qkvT, TDIM, 0, Xs, Rs, rg, cg);
    __syncthreads();
    dwconv(Rs, Qs, dw_w, 0, tid);
    __syncthreads();
    // ---- k ----
    gemm192v2(g_qkvT, TDIM, DIM, Xs, Rs, rg, cg);
    __syncthreads();
    dwconv(Rs, Ks, dw_w, DIM, tid);
    __syncthreads();

    // ---- l2 normalize q, k over 64 pixels (rsums in As[0..384)) ----
    for (int r = tid; r < 2 * DIM; r += NTHR) As[r] = 0.f;
    __syncthreads();
    for (int v = tid; v < 2 * 3072; v += NTHR) {
        int which = v >= 3072;
        int f = v - which * 3072;
        const float4* t4 = (const float4*)(which ? Ks : Qs);
        float4 q = t4[f];
        float ss = q.x * q.x + q.y * q.y + q.z * q.z + q.w * q.w;
        ss += __shfl_xor_sync(0xffffffffu, ss, 8);
        ss += __shfl_xor_sync(0xffffffffu, ss, 4);
        ss += __shfl_xor_sync(0xffffffffu, ss, 2);
        ss += __shfl_xor_sync(0xffffffffu, ss, 1);
        if ((lane & 15) == 0) atomicAdd(&As[which * DIM + (f >> 4)], ss);
    }
    __syncthreads();
    for (int r = tid; r < 2 * DIM; r += NTHR)
        As[r] = 1.f / fmaxf(sqrtf(As[r]), 1e-12f);
    __syncthreads();
    for (int v = tid; v < 2 * 3072; v += NTHR) {
        int which = v >= 3072;
        int f = v - which * 3072;
        float4* t4 = (float4*)(which ? Ks : Qs);
        float sc = As[which * DIM + (f >> 4)];
        float4 q = t4[f];
        q.x *= sc; q.y *= sc; q.z *= sc; q.w *= sc;
        t4[f] = q;
    }
    __syncthreads();

    // ---- attn scores: As[row][d] = (q_row . k_{head,d}) * temp[head] ----
    {
        float aacc[6][2];
#pragma unroll
        for (int r = 0; r < 6; r++) { aacc[r][0] = 0.f; aacc[r][1] = 0.f; }
        const float4* q4 = (const float4*)Qs;
        const float4* k4 = (const float4*)Ks;
#pragma unroll 2
        for (int p4 = 0; p4 < 16; p4++) {
#pragma unroll
            for (int r = 0; r < 6; r++) {
                int row = rg * 6 + r;
                int base = row & ~31;
                float4 qv = q4[row * 16 + p4];
#pragma unroll
                for (int cI = 0; cI < 2; cI++) {
                    float4 kv = k4[(base + cg * 2 + cI) * 16 + p4];
                    aacc[r][cI] += qv.x * kv.x + qv.y * kv.y + qv.z * kv.z + qv.w * kv.w;
                }
            }
        }
        __syncthreads();
#pragma unroll
        for (int r = 0; r < 6; r++) {
            int row = rg * 6 + r;
            float tmp = __ldg(temperature + (row >> 5));
            As[row * 32 + cg * 2]     = aacc[r][0] * tmp;
            As[row * 32 + cg * 2 + 1] = aacc[r][1] * tmp;
        }
    }
    __syncthreads();

    // ---- softmax over d (32), one row per thread ----
    if (tid < DIM) {
        float* arow = As + tid * 32;
        float m = arow[0];
#pragma unroll
        for (int d = 1; d < 32; d++) m = fmaxf(m, arow[d]);
        float s = 0.f;
#pragma unroll
        for (int d = 0; d < 32; d++) { float e = expf(arow[d] - m); arow[d] = e; s += e; }
        float inv = 1.f / s;
#pragma unroll
        for (int d = 0; d < 32; d++) arow[d] *= inv;
    }
    __syncthreads();

    // ---- v ----
    gemm192v2(g_qkvT, TDIM, 2 * DIM, Xs, Rs, rg, cg);
    __syncthreads();
    dwconv(Rs, Ks, dw_w, 2 * DIM, tid);   // V into Ks
    __syncthreads();

    // ---- out = attn @ v  -> Qs (f32x2 on column pairs) ----
    {
        ull acc2[6][2];
#pragma unroll
        for (int r = 0; r < 6; r++) { acc2[r][0] = 0ull; acc2[r][1] = 0ull; }
        const ull* v8 = (const ull*)Ks;
        for (int d = 0; d < 32; d++) {
#pragma unroll
            for (int r = 0; r < 6; r++) {
                int row = rg * 6 + r;
                int base = row & ~31;
                ull ad = dup2(As[row * 32 + d]);
                int vb = ((base + d) * 16 + cg) * 2;
                ffma2(acc2[r][0], v8[vb], ad);
                ffma2(acc2[r][1], v8[vb + 1], ad);
            }
        }
        float4* o4 = (float4*)Qs;
#pragma unroll
        for (int r = 0; r < 6; r++) {
            float2 a = ull2f2(acc2[r][0]), b = ull2f2(acc2[r][1]);
            o4[(rg * 6 + r) * 16 + cg] = make_float4(a.x, a.y, b.x, b.y);
        }
    }
    __syncthreads();

    // ---- proj GEMM (f32x2), store to gmem with roll(+4, +4) ----
    {
        ull acc[3][4];
#pragma unroll
        for (int p = 0; p < 3; p++)
#pragma unroll
            for (int j = 0; j < 4; j++) acc[p][j] = 0ull;
        const float4* s4 = (const float4*)Qs;
#pragma unroll 4
        for (int c = 0; c < DIM; c++) {
            float4 xv = s4[c * 16 + cg];
            const ull* wrow = (const ull*)(g_projT + (size_t)c * DIM + rg * 6);
            ull w0 = __ldg(wrow), w1 = __ldg(wrow + 1), w2 = __ldg(wrow + 2);
            ull xd0 = dup2(xv.x), xd1 = dup2(xv.y), xd2 = dup2(xv.z), xd3 = dup2(xv.w);
            ffma2(acc[0][0], w0, xd0); ffma2(acc[1][0], w1, xd0); ffma2(acc[2][0], w2, xd0);
            ffma2(acc[0][1], w0, xd1); ffma2(acc[1][1], w1, xd1); ffma2(acc[2][1], w2, xd1);
            ffma2(acc[0][2], w0, xd2); ffma2(acc[1][2], w1, xd2); ffma2(acc[2][2], w2, xd2);
            ffma2(acc[0][3], w0, xd3); ffma2(acc[1][3], w1, xd3); ffma2(acc[2][3], w2, xd3);
        }
        // cols cg*4+u all share window-row i = cg>>1
        int gh = (wh * WSZ + (cg >> 1) + SHIFTV) & 255;
#pragma unroll
        for (int p = 0; p < 3; p++) {
            float2 f0 = ull2f2(acc[p][0]), f1 = ull2f2(acc[p][1]);
            float2 f2 = ull2f2(acc[p][2]), f3 = ull2f2(acc[p][3]);
            float v0[4] = {f0.x, f1.x, f2.x, f3.x};
            float v1[4] = {f0.y, f1.y, f2.y, f3.y};
            int o0 = rg * 6 + 2 * p;
            float* orow0 = out + ((size_t)(bi * DIM + o0) * IMG + gh) * IMG;
            float* orow1 = out + ((size_t)(bi * DIM + o0 + 1) * IMG + gh) * IMG;
#pragma unroll
            for (int u = 0; u < 4; u++) {
                int j = ((cg & 1) * 4 + u);
                int gw = (ww * WSZ + j + SHIFTV) & 255;
                orow0[gw] = v0[u];
                orow1[gw] = v1[u];
            }
        }
    }
}

extern "C" void kernel_launch(void* const* d_in, const int* in_sizes, int n_in,
                              void* d_out, int out_size) {
    const float* x           = (const float*)d_in[0];
    const float* qkv_w       = (const float*)d_in[1];
    const float* dw_w        = (const float*)d_in[2];
    const float* proj_w      = (const float*)d_in[3];
    const float* temperature = (const float*)d_in[4];
    float* out = (float*)d_out;

    cudaFuncSetAttribute(attn_kernel, cudaFuncAttributeMaxDynamicSharedMemorySize,
                         SMEM_FLOATS * 4);
    wtrans_kernel<<<(TDIM * DIM + 255) / 256, 256>>>(qkv_w, proj_w);
    attn_kernel<<<4096, NTHR, SMEM_FLOATS * 4>>>(x, dw_w, temperature, out);
}

// round 3
// speedup vs baseline: 1.3068x; 1.1008x over previous
#include <cuda_runtime.h>

#define DIM   192
#define TDIM  576
#define WSZ   8
#define PIX   64
#define IMG   256
#define SHIFTV 4
#define NTHR  512

// smem layout (floats)
#define XS_OFF 0          // window input, later attention output [192][64]
#define QS_OFF 12288      // raw q -> conv q (in place)
#define KS_OFF 24576      // raw k -> conv k
#define VS_OFF 36864      // raw v -> conv v
#define AS_OFF 49152      // attn scores [192][32]
#define NS_OFF 55296      // inv norms [384]
#define SMEM_FLOATS 55680 // 222720 bytes

typedef unsigned long long ull;

__device__ float g_qkvT[DIM * TDIM];   // [c][o]
__device__ float g_projT[DIM * DIM];   // [c][o]

__global__ void wtrans_kernel(const float* __restrict__ qkv_w,
                              const float* __restrict__ proj_w) {
    int i = blockIdx.x * 256 + threadIdx.x;
    if (i < TDIM * DIM) {
        int o = i / DIM, c = i % DIM;
        g_qkvT[c * TDIM + o] = qkv_w[i];
    }
    if (i < DIM * DIM) {
        int o = i / DIM, c = i % DIM;
        g_projT[c * DIM + o] = proj_w[i];
    }
}

__device__ __forceinline__ ull dup2(float v) {
    ull r;
    asm("mov.b64 %0, {%1, %1};" : "=l"(r) : "f"(v));
    return r;
}
__device__ __forceinline__ void ffma2(ull& d, ull a, ull b) {
    asm("fma.rn.f32x2 %0, %1, %2, %0;" : "+l"(d) : "l"(a), "l"(b));
}
__device__ __forceinline__ float2 ull2f2(ull v) {
    float2 r;
    asm("mov.b64 {%0, %1}, %2;" : "=f"(r.x), "=f"(r.y) : "l"(v));
    return r;
}

__global__ void __launch_bounds__(NTHR, 1)
attn_kernel(const float* __restrict__ x, const float* __restrict__ dw_w,
            const float* __restrict__ temperature, float* __restrict__ out) {
    extern __shared__ float sm[];
    float* Xs = sm + XS_OFF;
    float* Qs = sm + QS_OFF;
    float* Ks = sm + KS_OFF;
    float* Vs = sm + VS_OFF;
    float* As = sm + AS_OFF;
    float* Ns = sm + NS_OFF;

    const int tid = threadIdx.x;
    const int win = blockIdx.x;
    const int bi = win >> 10;
    const int wh = (win >> 5) & 31;
    const int ww = win & 31;
    const int rg = tid >> 4;   // 32 groups of 6 rows
    const int cg = tid & 15;   // 16 float4 columns
    const int lane = tid & 31;
    const int wid = tid >> 5;  // 16 warps

    // ---- load window with roll(-4, -4) ----
    {
        const float* xb = x + (size_t)bi * DIM * IMG * IMG;
        for (int e = tid; e < DIM * PIX; e += NTHR) {
            int c = e >> 6, p = e & 63;
            int i = p >> 3, j = p & 7;
            int gh = (wh * WSZ + i + SHIFTV) & 255;
            int gw = (ww * WSZ + j + SHIFTV) & 255;
            Xs[e] = xb[(c * IMG + gh) * IMG + gw];
        }
    }
    __syncthreads();

    // ---- fused qkv GEMM: one x read feeds all 3 weight slices ----
    {
        ull acc[3][3][4];
#pragma unroll
        for (int s = 0; s < 3; s++)
#pragma unroll
            for (int p = 0; p < 3; p++)
#pragma unroll
                for (int j = 0; j < 4; j++) acc[s][p][j] = 0ull;
        const float4* s4 = (const float4*)Xs;
#pragma unroll 2
        for (int c = 0; c < DIM; c++) {
            float4 xv = s4[c * 16 + cg];
            ull xd0 = dup2(xv.x), xd1 = dup2(xv.y), xd2 = dup2(xv.z), xd3 = dup2(xv.w);
            const float* wbase = g_qkvT + (size_t)c * TDIM + rg * 6;
#pragma unroll
            for (int s = 0; s < 3; s++) {
                const ull* wrow = (const ull*)(wbase + s * DIM);
                ull w0 = __ldg(wrow), w1 = __ldg(wrow + 1), w2 = __ldg(wrow + 2);
                ffma2(acc[s][0][0], w0, xd0); ffma2(acc[s][1][0], w1, xd0); ffma2(acc[s][2][0], w2, xd0);
                ffma2(acc[s][0][1], w0, xd1); ffma2(acc[s][1][1], w1, xd1); ffma2(acc[s][2][1], w2, xd1);
                ffma2(acc[s][0][2], w0, xd2); ffma2(acc[s][1][2], w1, xd2); ffma2(acc[s][2][2], w2, xd2);
                ffma2(acc[s][0][3], w0, xd3); ffma2(acc[s][1][3], w1, xd3); ffma2(acc[s][2][3], w2, xd3);
            }
        }
        float* dsts[3] = {Qs, Ks, Vs};
#pragma unroll
        for (int s = 0; s < 3; s++) {
            float4* d4 = (float4*)dsts[s];
#pragma unroll
            for (int p = 0; p < 3; p++) {
                float2 f0 = ull2f2(acc[s][p][0]), f1 = ull2f2(acc[s][p][1]);
                float2 f2 = ull2f2(acc[s][p][2]), f3 = ull2f2(acc[s][p][3]);
                d4[(rg * 6 + 2 * p) * 16 + cg]     = make_float4(f0.x, f1.x, f2.x, f3.x);
                d4[(rg * 6 + 2 * p + 1) * 16 + cg] = make_float4(f0.y, f1.y, f2.y, f3.y);
            }
        }
    }
    __syncthreads();

    // ---- dwconv 3x3 in place, warp-per-channel, fused sumsq for q,k ----
    {
        int i0 = lane >> 3, j0 = lane & 7;       // pixel p0 = lane
        int i1 = (lane + 32) >> 3, j1 = lane & 7; // pixel p1 = lane + 32
#pragma unroll 2
        for (int it = 0; it < 36; it++) {
            int ch = it * 16 + wid;              // 0..575
            float* buf = (ch < 192) ? Qs : (ch < 384) ? Ks : Vs;
            int c = (ch < 192) ? ch : (ch < 384) ? ch - 192 : ch - 384;
            float* rr = buf + c * 64;
            const float* wd = dw_w + (size_t)ch * 9;
            float w[9];
#pragma unroll
            for (int u = 0; u < 9; u++) w[u] = __ldg(wd + u);
            float o0 = 0.f, o1 = 0.f;
#pragma unroll
            for (int di = 0; di < 3; di++) {
#pragma unroll
                for (int dj = 0; dj < 3; dj++) {
                    int jj = j0 + dj - 1;
                    if ((unsigned)jj < 8u) {
                        int ia = i0 + di - 1;
                        if ((unsigned)ia < 8u) o0 += rr[ia * 8 + jj] * w[di * 3 + dj];
                        int ib = i1 + di - 1;
                        if ((unsigned)ib < 8u) o1 += rr[ib * 8 + jj] * w[di * 3 + dj];
                    }
                }
            }
            __syncwarp();
            rr[lane] = o0;
            rr[lane + 32] = o1;
            if (ch < 384) {
                float ss = o0 * o0 + o1 * o1;
                ss += __shfl_xor_sync(0xffffffffu, ss, 16);
                ss += __shfl_xor_sync(0xffffffffu, ss, 8);
                ss += __shfl_xor_sync(0xffffffffu, ss, 4);
                ss += __shfl_xor_sync(0xffffffffu, ss, 2);
                ss += __shfl_xor_sync(0xffffffffu, ss, 1);
                if (lane == 0) Ns[ch] = 1.f / fmaxf(sqrtf(ss), 1e-12f);
            }
            __syncwarp();
        }
    }
    __syncthreads();

    // ---- attn scores on RAW q,k; scale by invq*invk*temp at store ----
    {
        float aacc[6][2];
#pragma unroll
        for (int r = 0; r < 6; r++) { aacc[r][0] = 0.f; aacc[r][1] = 0.f; }
        const float4* q4 = (const float4*)Qs;
        const float4* k4 = (const float4*)Ks;
#pragma unroll 2
        for (int p4 = 0; p4 < 16; p4++) {
#pragma unroll
            for (int r = 0; r < 6; r++) {
                int row = rg * 6 + r;
                int base = row & ~31;
                float4 qv = q4[row * 16 + p4];
#pragma unroll
                for (int cI = 0; cI < 2; cI++) {
                    float4 kv = k4[(base + cg * 2 + cI) * 16 + p4];
                    aacc[r][cI] += qv.x * kv.x + qv.y * kv.y + qv.z * kv.z + qv.w * kv.w;
                }
            }
        }
#pragma unroll
        for (int r = 0; r < 6; r++) {
            int row = rg * 6 + r;
            int base = row & ~31;
            float tmp = __ldg(temperature + (row >> 5));
            float invq = Ns[row];
#pragma unroll
            for (int cI = 0; cI < 2; cI++) {
                int kc = base + cg * 2 + cI;
                As[row * 32 + cg * 2 + cI] = aacc[r][cI] * invq * Ns[192 + kc] * tmp;
            }
        }
    }
    __syncthreads();

    // ---- softmax over d (32), one row per thread ----
    if (tid < DIM) {
        float* arow = As + tid * 32;
        float m = arow[0];
#pragma unroll
        for (int d = 1; d < 32; d++) m = fmaxf(m, arow[d]);
        float s = 0.f;
#pragma unroll
        for (int d = 0; d < 32; d++) { float e = expf(arow[d] - m); arow[d] = e; s += e; }
        float inv = 1.f / s;
#pragma unroll
        for (int d = 0; d < 32; d++) arow[d] *= inv;
    }
    __syncthreads();

    // ---- out = attn @ v -> Xs ----
    {
        ull acc2[6][2];
#pragma unroll
        for (int r = 0; r < 6; r++) { acc2[r][0] = 0ull; acc2[r][1] = 0ull; }
        const ull* v8 = (const ull*)Vs;
        for (int d = 0; d < 32; d++) {
#pragma unroll
            for (int r = 0; r < 6; r++) {
                int row = rg * 6 + r;
                int base = row & ~31;
                ull ad = dup2(As[row * 32 + d]);
                int vb = ((base + d) * 16 + cg) * 2;
                ffma2(acc2[r][0], v8[vb], ad);
                ffma2(acc2[r][1], v8[vb + 1], ad);
            }
        }
        float4* o4 = (float4*)Xs;
#pragma unroll
        for (int r = 0; r < 6; r++) {
            float2 a = ull2f2(acc2[r][0]), b = ull2f2(acc2[r][1]);
            o4[(rg * 6 + r) * 16 + cg] = make_float4(a.x, a.y, b.x, b.y);
        }
    }
    __syncthreads();

    // ---- proj GEMM, store to gmem with roll(+4, +4) ----
    {
        ull acc[3][4];
#pragma unroll
        for (int p = 0; p < 3; p++)
#pragma unroll
            for (int j = 0; j < 4; j++) acc[p][j] = 0ull;
        const float4* s4 = (const float4*)Xs;
#pragma unroll 4
        for (int c = 0; c < DIM; c++) {
            float4 xv = s4[c * 16 + cg];
            const ull* wrow = (const ull*)(g_projT + (size_t)c * DIM + rg * 6);
            ull w0 = __ldg(wrow), w1 = __ldg(wrow + 1), w2 = __ldg(wrow + 2);
            ull xd0 = dup2(xv.x), xd1 = dup2(xv.y), xd2 = dup2(xv.z), xd3 = dup2(xv.w);
            ffma2(acc[0][0], w0, xd0); ffma2(acc[1][0], w1, xd0); ffma2(acc[2][0], w2, xd0);
            ffma2(acc[0][1], w0, xd1); ffma2(acc[1][1], w1, xd1); ffma2(acc[2][1], w2, xd1);
            ffma2(acc[0][2], w0, xd2); ffma2(acc[1][2], w1, xd2); ffma2(acc[2][2], w2, xd2);
            ffma2(acc[0][3], w0, xd3); ffma2(acc[1][3], w1, xd3); ffma2(acc[2][3], w2, xd3);
        }
        int gh = (wh * WSZ + (cg >> 1) + SHIFTV) & 255;
#pragma unroll
        for (int p = 0; p < 3; p++) {
            float2 f0 = ull2f2(acc[p][0]), f1 = ull2f2(acc[p][1]);
            float2 f2 = ull2f2(acc[p][2]), f3 = ull2f2(acc[p][3]);
            float v0[4] = {f0.x, f1.x, f2.x, f3.x};
            float v1[4] = {f0.y, f1.y, f2.y, f3.y};
            int o0 = rg * 6 + 2 * p;
            float* orow0 = out + ((size_t)(bi * DIM + o0) * IMG + gh) * IMG;
            float* orow1 = out + ((size_t)(bi * DIM + o0 + 1) * IMG + gh) * IMG;
#pragma unroll
            for (int u = 0; u < 4; u++) {
                int j = ((cg & 1) * 4 + u);
                int gw = (ww * WSZ + j + SHIFTV) & 255;
                orow0[gw] = v0[u];
                orow1[gw] = v1[u];
            }
        }
    }
}

extern "C" void kernel_launch(void* const* d_in, const int* in_sizes, int n_in,
                              void* d_out, int out_size) {
    const float* x           = (const float*)d_in[0];
    const float* qkv_w       = (const float*)d_in[1];
    const float* dw_w        = (const float*)d_in[2];
    const float* proj_w      = (const float*)d_in[3];
    const float* temperature = (const float*)d_in[4];
    float* out = (float*)d_out;

    cudaFuncSetAttribute(attn_kernel, cudaFuncAttributeMaxDynamicSharedMemorySize,
                         SMEM_FLOATS * 4);
    wtrans_kernel<<<(TDIM * DIM + 255) / 256, 256>>>(qkv_w, proj_w);
    attn_kernel<<<4096, NTHR, SMEM_FLOATS * 4>>>(x, dw_w, temperature, out);
}